// round 4
// baseline (speedup 1.0000x reference)
#include <cuda_runtime.h>
#include <math.h>

#define BATCH 32
#define HH 256
#define WW 256
#define IMGPIX 65536
#define NPIX (BATCH*IMGPIX)
#define IMGWORDS (IMGPIX/32)     // 2048
#define NWORDS (NPIX/32)         // 65536
#define INF_I 10000
#define ROW_BLOCKS 256           // 32 images x 8 bands of 32 rows

__device__ unsigned int   g_tgm[NWORDS];
__device__ unsigned int   g_fatm[NWORDS];
__device__ unsigned short g_gv[NPIX];
__device__ int   g_bmin[ROW_BLOCKS];
__device__ int   g_bmax[ROW_BLOCKS];
__device__ int   g_fg[BATCH];
__device__ float g_s1[ROW_BLOCKS], g_s2[ROW_BLOCKS], g_s4[ROW_BLOCKS];
__device__ float g_s5[ROW_BLOCKS], g_s6[ROW_BLOCKS], g_s7[ROW_BLOCKS];

__device__ __forceinline__ float fsum32(float v) {
#pragma unroll
    for (int s = 16; s > 0; s >>= 1) v += __shfl_down_sync(0xffffffffu, v, s);
    return v;
}
__device__ __forceinline__ int imin32(int v) {
#pragma unroll
    for (int s = 16; s > 0; s >>= 1) v = min(v, __shfl_down_sync(0xffffffffu, v, s));
    return v;
}
__device__ __forceinline__ int imax32(int v) {
#pragma unroll
    for (int s = 16; s > 0; s >>= 1) v = max(v, __shfl_down_sync(0xffffffffu, v, s));
    return v;
}
__device__ __forceinline__ unsigned int ior32(unsigned int v) {
#pragma unroll
    for (int s = 16; s > 0; s >>= 1) v |= __shfl_down_sync(0xffffffffu, v, s);
    return v;
}

// ---- K1: tg -> bitmask (full chip, 1024 blocks x 256 thr) ----
__global__ void k_mask(const float* __restrict__ tg) {
    const int lane = threadIdx.x & 31;
    const int warp = (blockIdx.x << 3) | (threadIdx.x >> 5);  // 8192 warps
#pragma unroll
    for (int k = 0; k < 8; k++) {
        int w = warp * 8 + k;                     // word index 0..65535
        float v = tg[w * 32 + lane];
        unsigned int word = __ballot_sync(0xffffffffu, v > 0.5f);
        if (lane == 0) g_tgm[w] = word;
    }
}

// ---- K2: bitwise 5x5 dilation + vertical two-pass scan (32 blocks x 256 thr) ----
// dynamic smem: tg[2048] u32, hw[2048] u32, fat[2048] u32, gf[65536] u16
__global__ void __launch_bounds__(256, 1) k_vscan() {
    extern __shared__ unsigned int sm[];
    unsigned int* tgw = sm;
    unsigned int* hw  = sm + IMGWORDS;
    unsigned int* fat = sm + 2 * IMGWORDS;
    unsigned short* gf = reinterpret_cast<unsigned short*>(sm + 3 * IMGWORDS);
    __shared__ unsigned int s_or[8];
    const int tid = threadIdx.x;
    const int img = blockIdx.x;

    unsigned int any = 0u;
#pragma unroll
    for (int k = 0; k < 8; k++) {
        int w = tid + k * 256;
        unsigned int v = g_tgm[img * IMGWORDS + w];
        tgw[w] = v; any |= v;
    }
    any = ior32(any);
    if ((tid & 31) == 0) s_or[tid >> 5] = any;
    __syncthreads();
    if (tid == 0) {
        unsigned int a = 0;
#pragma unroll
        for (int i = 0; i < 8; i++) a |= s_or[i];
        g_fg[img] = a ? 1 : 0;
    }

    // horizontal 5-dilate (bitwise)
#pragma unroll
    for (int k = 0; k < 8; k++) {
        int w = tid + k * 256;
        int wc = w & 7;
        unsigned int c  = tgw[w];
        unsigned int ml = (wc > 0) ? tgw[w - 1] : 0u;
        unsigned int mr = (wc < 7) ? tgw[w + 1] : 0u;
        unsigned int h = c;
        h |= (c << 1) | (ml >> 31);
        h |= (c << 2) | (ml >> 30);
        h |= (c >> 1) | (mr << 31);
        h |= (c >> 2) | (mr << 30);
        hw[w] = h;
    }
    __syncthreads();
    // vertical 5-dilate
#pragma unroll
    for (int k = 0; k < 8; k++) {
        int w = tid + k * 256;
        int row = w >> 3;
        unsigned int f = hw[w];
        if (row >= 1)      f |= hw[w - 8];
        if (row >= 2)      f |= hw[w - 16];
        if (row <= HH - 2) f |= hw[w + 8];
        if (row <= HH - 3) f |= hw[w + 16];
        fat[w] = f;
        g_fatm[img * IMGWORDS + w] = f;
    }
    __syncthreads();

    // per-column two-pass distance
    const int j = tid;
    const int wsel = j >> 5, bsel = j & 31;
    int d = INF_I;
#pragma unroll 4
    for (int h = 0; h < HH; h++) {
        int bit = (fat[(h << 3) | wsel] >> bsel) & 1;
        d = bit ? min(d + 1, INF_I) : 0;
        gf[h * WW + j] = (unsigned short)d;
    }
    d = INF_I;
#pragma unroll 4
    for (int h = HH - 1; h >= 0; h--) {
        int bit = (fat[(h << 3) | wsel] >> bsel) & 1;
        d = bit ? min(d + 1, INF_I) : 0;
        int m = min((int)gf[h * WW + j], d);
        g_gv[img * IMGPIX + h * WW + j] = (unsigned short)m;
    }
}

// ---- K3: fused pruned min-plus + sigmoid + linear dice partials ----
// 256 blocks (img x 8 bands of 32 rows) x 256 thr
__global__ void k_rowfuse(const float* __restrict__ preds) {
    __shared__ unsigned short tile[32 * WW];
    __shared__ unsigned int stg[256], sfat[256];
    __shared__ float sf[8];
    __shared__ int smn[8], smx[8];
    const int tid = threadIdx.x;
    const int img = blockIdx.x >> 3;
    const int band = blockIdx.x & 7;
    const int base = img * IMGPIX + band * 32 * WW;
    const int wbase = img * IMGWORDS + band * 256;

#pragma unroll 8
    for (int k = 0; k < 32; k++) tile[k * WW + tid] = g_gv[base + k * WW + tid];
    stg[tid]  = g_tgm[wbase + tid];
    sfat[tid] = g_fatm[wbase + tid];
    __syncthreads();

    const int j = tid;
    const int wsel = j >> 5, bsel = j & 31;
    float s1 = 0, s2 = 0, s4 = 0, s5 = 0, s6 = 0, s7 = 0;
    int mn = 0x7fffffff, mx = 0;
#pragma unroll 1
    for (int r = 0; r < 32; r++) {
        const unsigned short* grow = tile + r * WW;
        int g0 = grow[j];
        int best = g0 * g0;
        for (int rad = 1; rad < WW; rad++) {
            int r2 = rad * rad;
            if (r2 >= best) break;
            int jl = j - rad, jr = j + rad;
            if (jl >= 0) { int gv = grow[jl]; best = min(best, gv * gv + r2); }
            if (jr < WW) { int gv = grow[jr]; best = min(best, gv * gv + r2); }
        }
        mn = min(mn, best); mx = max(mx, best);
        float dist = sqrtf((float)best);
        float soft = 1.0f / (1.0f + __expf(-dist * 0.2f));
        float p = 1.0f / (1.0f + __expf(-preds[base + r * WW + j]));
        float t    = (float)((stg[(r << 3) | wsel]  >> bsel) & 1u);
        float fatb = (float)((sfat[(r << 3) | wsel] >> bsel) & 1u);
        float ps = p * soft;
        s1 += ps * t;
        s2 += p * t;
        s4 += ps;
        s5 += p;
        s6 += p * (1.0f - fatb);
        s7 += t;
    }
    mn = imin32(mn); mx = imax32(mx);
    if ((tid & 31) == 0) { smn[tid >> 5] = mn; smx[tid >> 5] = mx; }

    float vals[6] = {s1, s2, s4, s5, s6, s7};
    float* outs[6] = {g_s1, g_s2, g_s4, g_s5, g_s6, g_s7};
#pragma unroll
    for (int q = 0; q < 6; q++) {
        float v = fsum32(vals[q]);
        __syncthreads();
        if ((tid & 31) == 0) sf[tid >> 5] = v;
        __syncthreads();
        if (tid == 0) {
            float a = 0;
#pragma unroll
            for (int i = 0; i < 8; i++) a += sf[i];
            outs[q][blockIdx.x] = a;
        }
    }
    if (tid == 0) {
        int a = smn[0], b = smx[0];
#pragma unroll
        for (int i = 1; i < 8; i++) { a = min(a, smn[i]); b = max(b, smx[i]); }
        g_bmin[blockIdx.x] = a; g_bmax[blockIdx.x] = b;
    }
}

// ---- K4: per-image normalization + final dice (1 warp, lane = image) ----
__global__ void k_out(float* out) {
    const int i = threadIdx.x;      // image index, 32 lanes
    float S1 = 0, S2 = 0, S4 = 0, S5 = 0, S6 = 0, S7 = 0;
    int mn = 0x7fffffff, mx = 0;
#pragma unroll
    for (int b = 0; b < 8; b++) {
        int k = i * 8 + b;
        S1 += g_s1[k]; S2 += g_s2[k]; S4 += g_s4[k];
        S5 += g_s5[k]; S6 += g_s6[k]; S7 += g_s7[k];
        mn = min(mn, g_bmin[k]); mx = max(mx, g_bmax[k]);
    }
    float inter, card;
    if (g_fg[i]) {
        float smn = 1.0f / (1.0f + __expf(-sqrtf((float)mn) * 0.2f));
        float smx = 1.0f / (1.0f + __expf(-sqrtf((float)mx) * 0.2f));
        float dd = smx - smn;
        float inv = (dd > 0.0f) ? (1.0f / dd) : 1.0f;
        inter = inv * (S1 - smn * S2);
        card  = inv * (S4 - smn * S5) + 0.1f * S6 + S7;
    } else {
        inter = 0.0f;
        card  = (S5 - S2) + S7;
    }
    float tsum = S7;
    inter = fsum32(inter);
    card  = fsum32(card);
    tsum  = fsum32(tsum);
    if (i == 0) {
        float dice = 2.0f * inter / fmaxf(card, 1e-7f);
        float loss = 1.0f - dice;
        out[0] = (tsum > 0.0f) ? loss : 0.0f;
    }
}

extern "C" void kernel_launch(void* const* d_in, const int* in_sizes, int n_in,
                              void* d_out, int out_size) {
    const float* preds = (const float*)d_in[0];
    const float* tg    = (const float*)d_in[1];
    float* out = (float*)d_out;

    const int vs_smem = 3 * IMGWORDS * 4 + IMGPIX * 2;   // 24KB + 128KB
    cudaFuncSetAttribute(k_vscan, cudaFuncAttributeMaxDynamicSharedMemorySize, vs_smem);

    k_mask<<<1024, 256>>>(tg);
    k_vscan<<<BATCH, 256, vs_smem>>>();
    k_rowfuse<<<ROW_BLOCKS, 256>>>(preds);
    k_out<<<1, 32>>>(out);
}

// round 5
// speedup vs baseline: 1.3157x; 1.3157x over previous
#include <cuda_runtime.h>
#include <math.h>

#define BATCH 32
#define HH 256
#define WW 256
#define IMGPIX 65536
#define NPIX (BATCH*IMGPIX)
#define IMGWORDS 2048            // 32-bit words per image (row-major mask)
#define NWORDS (BATCH*IMGWORDS)
#define INF_I 10000
#define K1B 256                  // 32 img x 8 rowgroups of 32 rows
#define RB   1024                // 32 img x 32 bands of 8 rows

__device__ unsigned int g_tgm[NWORDS];
__device__ unsigned int g_fatm[NWORDS];
__device__ unsigned int g_fatT[BATCH * 8 * 256];   // [img][rowword 0..7][col]
__device__ int   g_fgp[K1B];
__device__ int   g_bmin[RB], g_bmax[RB];
__device__ float g_s1[RB], g_s2[RB], g_s4[RB], g_s5[RB], g_s6[RB], g_s7[RB];

__device__ __forceinline__ float fsum32(float v) {
#pragma unroll
    for (int s = 16; s > 0; s >>= 1) v += __shfl_down_sync(0xffffffffu, v, s);
    return v;
}
__device__ __forceinline__ int imin32(int v) {
#pragma unroll
    for (int s = 16; s > 0; s >>= 1) v = min(v, __shfl_down_sync(0xffffffffu, v, s));
    return v;
}
__device__ __forceinline__ int imax32(int v) {
#pragma unroll
    for (int s = 16; s > 0; s >>= 1) v = max(v, __shfl_down_sync(0xffffffffu, v, s));
    return v;
}
__device__ __forceinline__ unsigned int ior32(unsigned int v) {
#pragma unroll
    for (int s = 16; s > 0; s >>= 1) v |= __shfl_down_sync(0xffffffffu, v, s);
    return v;
}

// distance (in rows) from position r to nearest 0-bit in 256-bit column mask m[8]
__device__ __forceinline__ int nzdist(const unsigned int* m, int r) {
    int w = r >> 5, b = r & 31;
    unsigned int inv0 = ~m[w];
    int dd;
    unsigned int x = inv0 >> b;                 // bit0 = position r
    if (x) dd = __ffs(x) - 1;
    else {
        dd = INF_I;
        for (int k = w + 1; k < 8; k++) {
            unsigned int xi = ~m[k];
            if (xi) { dd = k * 32 + __ffs(xi) - 1 - r; break; }
        }
    }
    int du;
    unsigned int y = inv0 << (31 - b);          // bit31 = position r
    if (y) du = __clz(y);
    else {
        du = INF_I;
        for (int k = w - 1; k >= 0; k--) {
            unsigned int yi = ~m[k];
            if (yi) { du = r - (k * 32 + 31 - __clz(yi)); break; }
        }
    }
    return min(min(dd, du), INF_I);
}

// ---- K1: ballot mask + bitwise 5x5 dilate + bit-transpose (256 blocks x 256 thr) ----
__global__ void k_dilate(const float* __restrict__ tg) {
    __shared__ unsigned int raw[36 * 8];   // raw tg words, rows r0-2 .. r0+33
    __shared__ unsigned int hm[36 * 8];    // horizontally dilated
    __shared__ unsigned int fatw[32 * 8];  // fully dilated, central rows
    __shared__ unsigned int s_fg[8];
    const int tid = threadIdx.x, lane = tid & 31, wid = tid >> 5;
    const int img = blockIdx.x >> 3, rg = blockIdx.x & 7;
    const int r0 = rg * 32;
    const int imgbase = img * IMGPIX;

    unsigned int fgacc = 0u;
#pragma unroll 4
    for (int lr = 0; lr < 36; lr++) {
        int grow = r0 - 2 + lr;
        unsigned int word = 0u;
        if (grow >= 0 && grow < HH) {
            float v = tg[imgbase + grow * WW + wid * 32 + lane];
            word = __ballot_sync(0xffffffffu, v > 0.5f);
        }
        raw[lr * 8 + wid] = word;                     // uniform across warp
        if (lr >= 2 && lr < 34) {
            fgacc |= word;
            if (lane == 0) g_tgm[img * IMGWORDS + (grow) * 8 + wid] = word;
        }
    }
    fgacc = ior32(fgacc);
    if (lane == 0) s_fg[wid] = fgacc;
    __syncthreads();
    if (tid == 0) {
        unsigned int a = 0;
#pragma unroll
        for (int i = 0; i < 8; i++) a |= s_fg[i];
        g_fgp[blockIdx.x] = a ? 1 : 0;
    }

    // horizontal 5-dilate (288 words)
    for (int w = tid; w < 288; w += 256) {
        int wc = w & 7;
        unsigned int c  = raw[w];
        unsigned int ml = (wc > 0) ? raw[w - 1] : 0u;
        unsigned int mr = (wc < 7) ? raw[w + 1] : 0u;
        unsigned int h = c;
        h |= (c << 1) | (ml >> 31);
        h |= (c << 2) | (ml >> 30);
        h |= (c >> 1) | (mr << 31);
        h |= (c >> 2) | (mr << 30);
        hm[w] = h;
    }
    __syncthreads();

    // vertical 5-dilate: output row rl uses hm rows rl..rl+4
    {
        int rl = tid >> 3, wc = tid & 7;
        unsigned int f = hm[rl * 8 + wc] | hm[(rl + 1) * 8 + wc] | hm[(rl + 2) * 8 + wc] |
                         hm[(rl + 3) * 8 + wc] | hm[(rl + 4) * 8 + wc];
        fatw[tid] = f;
        g_fatm[img * IMGWORDS + (r0 + rl) * 8 + wc] = f;
    }
    __syncthreads();

    // 32x32 bit transpose per word-column via ballot
    {
        unsigned int v = fatw[lane * 8 + wid];   // lane = row within group
        unsigned int myw = 0u;
#pragma unroll
        for (int c = 0; c < 32; c++) {
            unsigned int bw = __ballot_sync(0xffffffffu, (v >> c) & 1u);
            if (lane == c) myw = bw;
        }
        // col = wid*32 + lane, rowword = rg
        g_fatT[img * 2048 + rg * 256 + wid * 32 + lane] = myw;
    }
}

// ---- K2: fused vertical-dist + pruned min-plus + sigmoid + linear dice partials ----
// 1024 blocks (img x 32 bands of 8 rows) x 256 thr
__global__ void k_rowfuse(const float* __restrict__ preds) {
    __shared__ unsigned short tile[8 * WW];
    __shared__ unsigned int stgw[64], sfatw[64];
    __shared__ float sf[8];
    __shared__ int smn8[8], smx8[8];
    const int tid = threadIdx.x;
    const int img = blockIdx.x >> 5, band = blockIdx.x & 31;
    const int r0 = band * 8;
    const int base = img * IMGPIX + r0 * WW;
    const int wb = img * IMGWORDS + r0 * 8;

    if (tid < 64) { stgw[tid] = g_tgm[wb + tid]; sfatw[tid] = g_fatm[wb + tid]; }

    unsigned int m[8];
#pragma unroll
    for (int k = 0; k < 8; k++) m[k] = g_fatT[img * 2048 + k * 256 + tid];

#pragma unroll
    for (int i = 0; i < 8; i++) {
        int r = r0 + i;
        int d = ((m[r >> 5] >> (r & 31)) & 1u) ? nzdist(m, r) : 0;
        tile[i * WW + tid] = (unsigned short)d;
    }
    __syncthreads();

    const int j = tid;
    const int wsel = j >> 5, bsel = j & 31;
    float s1 = 0, s2 = 0, s4 = 0, s5 = 0, s6 = 0, s7 = 0;
    int mn = 0x7fffffff, mx = 0;
#pragma unroll 1
    for (int i = 0; i < 8; i++) {
        const unsigned short* grow = tile + i * WW;
        int g0 = grow[j];
        int best = g0 * g0;
        for (int rad = 1; rad < WW; rad++) {
            int r2 = rad * rad;
            if (r2 >= best) break;
            int jl = j - rad, jr = j + rad;
            if (jl >= 0) { int gv = grow[jl]; best = min(best, gv * gv + r2); }
            if (jr < WW) { int gv = grow[jr]; best = min(best, gv * gv + r2); }
        }
        mn = min(mn, best); mx = max(mx, best);
        float dist = sqrtf((float)best);
        float soft = 1.0f / (1.0f + __expf(-dist * 0.2f));
        float p = 1.0f / (1.0f + __expf(-preds[base + i * WW + j]));
        float t    = (float)((stgw[(i << 3) | wsel]  >> bsel) & 1u);
        float fatb = (float)((sfatw[(i << 3) | wsel] >> bsel) & 1u);
        float ps = p * soft;
        s1 += ps * t;
        s2 += p * t;
        s4 += ps;
        s5 += p;
        s6 += p * (1.0f - fatb);
        s7 += t;
    }
    mn = imin32(mn); mx = imax32(mx);
    if ((tid & 31) == 0) { smn8[tid >> 5] = mn; smx8[tid >> 5] = mx; }

    float vals[6] = {s1, s2, s4, s5, s6, s7};
    float* outs[6] = {g_s1, g_s2, g_s4, g_s5, g_s6, g_s7};
#pragma unroll
    for (int q = 0; q < 6; q++) {
        float v = fsum32(vals[q]);
        __syncthreads();
        if ((tid & 31) == 0) sf[tid >> 5] = v;
        __syncthreads();
        if (tid == 0) {
            float a = 0;
#pragma unroll
            for (int i = 0; i < 8; i++) a += sf[i];
            outs[q][blockIdx.x] = a;
        }
    }
    if (tid == 0) {
        int a = smn8[0], b = smx8[0];
#pragma unroll
        for (int i = 1; i < 8; i++) { a = min(a, smn8[i]); b = max(b, smx8[i]); }
        g_bmin[blockIdx.x] = a; g_bmax[blockIdx.x] = b;
    }
}

// ---- K3: final normalization + dice (1 block x 256 thr) ----
__global__ void k_out(float* out) {
    __shared__ float a1[256], a2[256], a4[256], a5[256], a6[256], a7[256];
    __shared__ int amn[256], amx[256];
    const int t = threadIdx.x;
    const int img = t >> 3, seg = t & 7;
    float S1 = 0, S2 = 0, S4 = 0, S5 = 0, S6 = 0, S7 = 0;
    int mn = 0x7fffffff, mx = 0;
#pragma unroll
    for (int q = 0; q < 4; q++) {
        int k = img * 32 + seg * 4 + q;
        S1 += g_s1[k]; S2 += g_s2[k]; S4 += g_s4[k];
        S5 += g_s5[k]; S6 += g_s6[k]; S7 += g_s7[k];
        mn = min(mn, g_bmin[k]); mx = max(mx, g_bmax[k]);
    }
    a1[t] = S1; a2[t] = S2; a4[t] = S4; a5[t] = S5; a6[t] = S6; a7[t] = S7;
    amn[t] = mn; amx[t] = mx;
    __syncthreads();
    if (t < 32) {
        const int i = t;   // image
        S1 = 0; S2 = 0; S4 = 0; S5 = 0; S6 = 0; S7 = 0;
        mn = 0x7fffffff; mx = 0;
#pragma unroll
        for (int s = 0; s < 8; s++) {
            int k = i * 8 + s;
            S1 += a1[k]; S2 += a2[k]; S4 += a4[k];
            S5 += a5[k]; S6 += a6[k]; S7 += a7[k];
            mn = min(mn, amn[k]); mx = max(mx, amx[k]);
        }
        int fg = 0;
#pragma unroll
        for (int rg = 0; rg < 8; rg++) fg |= g_fgp[i * 8 + rg];
        float inter, card;
        if (fg) {
            float smn = 1.0f / (1.0f + __expf(-sqrtf((float)mn) * 0.2f));
            float smx = 1.0f / (1.0f + __expf(-sqrtf((float)mx) * 0.2f));
            float dd = smx - smn;
            float inv = (dd > 0.0f) ? (1.0f / dd) : 1.0f;
            inter = inv * (S1 - smn * S2);
            card  = inv * (S4 - smn * S5) + 0.1f * S6 + S7;
        } else {
            inter = 0.0f;
            card  = (S5 - S2) + S7;
        }
        float tsum = S7;
        inter = fsum32(inter);
        card  = fsum32(card);
        tsum  = fsum32(tsum);
        if (i == 0) {
            float dice = 2.0f * inter / fmaxf(card, 1e-7f);
            float loss = 1.0f - dice;
            out[0] = (tsum > 0.0f) ? loss : 0.0f;
        }
    }
}

extern "C" void kernel_launch(void* const* d_in, const int* in_sizes, int n_in,
                              void* d_out, int out_size) {
    const float* preds = (const float*)d_in[0];
    const float* tg    = (const float*)d_in[1];
    float* out = (float*)d_out;

    k_dilate<<<K1B, 256>>>(tg);
    k_rowfuse<<<RB, 256>>>(preds);
    k_out<<<1, 256>>>(out);
}